// round 5
// baseline (speedup 1.0000x reference)
#include <cuda_runtime.h>
#include <cuda_bf16.h>
#include <cstdint>

#define NROWS 8192
#define DIM   128
#define CHUNK 128                  // samples per tile
#define NBLOCKS 128                // b<64: X chunk b (+diag); b>=64: Y chunk b-64

// ---------------- device-global scratch (no allocations allowed) -----------
// Zero at load; every launch restores the zeroed state before exiting.
__device__ float    g_G[2][DIM * DIM];  // [0]=X^T X, [1]=Y^T Y
__device__ float    g_S2;               // sum d_i^2
__device__ float    g_S3;               // sum d_i
__device__ unsigned g_ticket;

// ---------------- helpers ---------------------------------------------------
__device__ __forceinline__ uint32_t smem_u32(const void* p) {
    uint32_t a;
    asm("{ .reg .u64 t; cvta.to.shared.u64 t, %1; cvt.u32.u64 %0, t; }" : "=r"(a) : "l"(p));
    return a;
}

// Tile stored SAMPLE-major: S[k][d]; two 16KB subtiles by d>>6; SW128 swizzle.
__device__ __forceinline__ uint32_t toff(int k, int d) {
    uint32_t o = (uint32_t)(k * 128 + (d & 63) * 2);
    o ^= (o >> 3) & 0x70;
    return (uint32_t)((d >> 6) * 16384) + o;
}

#define LO_OFF     32768           // lo tile after hi tile (each 32KB)
#define SMEM_TOTAL 65536

__device__ __forceinline__ void ldsm4t(uint32_t* r, uint32_t addr) {
    asm volatile("ldmatrix.sync.aligned.m8n8.x4.trans.shared.b16 {%0,%1,%2,%3}, [%4];"
                 : "=r"(r[0]), "=r"(r[1]), "=r"(r[2]), "=r"(r[3]) : "r"(addr));
}

__device__ __forceinline__ void mma_bf16(float* d, const uint32_t* a,
                                         uint32_t b0, uint32_t b1) {
    asm volatile(
        "mma.sync.aligned.m16n8k16.row.col.f32.bf16.bf16.f32 "
        "{%0,%1,%2,%3}, {%4,%5,%6,%7}, {%8,%9}, {%0,%1,%2,%3};"
        : "+f"(d[0]), "+f"(d[1]), "+f"(d[2]), "+f"(d[3])
        : "r"(a[0]), "r"(a[1]), "r"(a[2]), "r"(a[3]), "r"(b0), "r"(b1));
}

// ---------------------------------------------------------------------------
// Single fused kernel: convert(+diag) -> tensor-core Gram -> atomic merge ->
// ticket -> last block: Frobenius reduce + combine + write + re-zero scratch.
// ---------------------------------------------------------------------------
__global__ __launch_bounds__(256, 1)
void gram_all(const float* __restrict__ X, const float* __restrict__ Y,
              float* __restrict__ out) {
    extern __shared__ char smem[];
    __shared__ double   sred[256];
    __shared__ unsigned s_last;

    const uint32_t sb = smem_u32(smem);
    const int tid  = threadIdx.x;
    const int w    = tid >> 5;
    const int lane = tid & 31;

    const bool isX  = blockIdx.x < (NBLOCKS / 2);
    const int chunk = isX ? blockIdx.x : blockIdx.x - NBLOCKS / 2;
    const float* base  = (isX ? X : Y) + (size_t)chunk * CHUNK * DIM;
    const float* ybase = Y + (size_t)chunk * CHUNK * DIM;   // for diag (X blocks)

    // ldmatrix per-lane tile-row selectors
    const int lr    = lane & 7;
    const int a_kad = (lane & 16) ? 8 : 0;
    const int a_mad = (lane & 8)  ? 8 : 0;
    const int b_kad = (lane & 8)  ? 8 : 0;
    const int b_nad = (lane & 16) ? 8 : 0;
    const int m0    = w * 16;

    // ---- convert fp32 -> bf16 hi/lo tiles; X blocks also compute diag ----
    float s2 = 0.0f, s3 = 0.0f;
    #pragma unroll 4
    for (int it = 0; it < 16; ++it) {
        const int r = w + 8 * it;                     // sample row
        const float4 v = *reinterpret_cast<const float4*>(base + r * DIM + lane * 4);
        __nv_bfloat162 h01 = __floats2bfloat162_rn(v.x, v.y);
        __nv_bfloat162 h23 = __floats2bfloat162_rn(v.z, v.w);
        __nv_bfloat162 l01 = __floats2bfloat162_rn(v.x - __bfloat162float(h01.x),
                                                   v.y - __bfloat162float(h01.y));
        __nv_bfloat162 l23 = __floats2bfloat162_rn(v.z - __bfloat162float(h23.x),
                                                   v.w - __bfloat162float(h23.y));
        const uint32_t o = toff(r, lane * 4);
        uint2 hv, lv;
        hv.x = *reinterpret_cast<uint32_t*>(&h01);
        hv.y = *reinterpret_cast<uint32_t*>(&h23);
        lv.x = *reinterpret_cast<uint32_t*>(&l01);
        lv.y = *reinterpret_cast<uint32_t*>(&l23);
        *reinterpret_cast<uint2*>(smem + o)          = hv;
        *reinterpret_cast<uint2*>(smem + LO_OFF + o) = lv;

        if (isX) {                                    // diag: d_r = <x_r, y_r>
            const float4 u = *reinterpret_cast<const float4*>(ybase + r * DIM + lane * 4);
            float d = v.x * u.x + v.y * u.y + v.z * u.z + v.w * u.w;
            #pragma unroll
            for (int o2 = 16; o2; o2 >>= 1) d += __shfl_xor_sync(0xffffffffu, d, o2);
            s3 += d;
            s2 += d * d;
        }
    }
    if (isX && lane == 0) {
        atomicAdd(&g_S3, s3);
        atomicAdd(&g_S2, s2);
    }
    __syncthreads();

    // ---- MMA mainloop: acc[nt][i], nt = 0..15 (8-col tiles) ----
    float acc[16][4];
    #pragma unroll
    for (int nt = 0; nt < 16; ++nt)
        #pragma unroll
        for (int i = 0; i < 4; ++i) acc[nt][i] = 0.0f;

    for (int ks = 0; ks < 8; ++ks) {
        const int k0 = ks * 16;
        uint32_t ahi[4], alo[4];
        const uint32_t aoff = toff(k0 + lr + a_kad, m0 + a_mad);
        ldsm4t(ahi, sb + aoff);
        ldsm4t(alo, sb + LO_OFF + aoff);

        #pragma unroll
        for (int ntp = 0; ntp < 8; ++ntp) {
            const int n0 = ntp * 16;
            uint32_t bhi[4], blo[4];
            const uint32_t boff = toff(k0 + lr + b_kad, n0 + b_nad);
            ldsm4t(bhi, sb + boff);
            ldsm4t(blo, sb + LO_OFF + boff);
            mma_bf16(acc[2 * ntp], ahi, bhi[0], bhi[1]);
            mma_bf16(acc[2 * ntp], ahi, blo[0], blo[1]);
            mma_bf16(acc[2 * ntp], alo, bhi[0], bhi[1]);
            mma_bf16(acc[2 * ntp + 1], ahi, bhi[2], bhi[3]);
            mma_bf16(acc[2 * ntp + 1], ahi, blo[2], blo[3]);
            mma_bf16(acc[2 * ntp + 1], alo, bhi[2], bhi[3]);
        }
    }

    // ---- merge partial Gram ----
    {
        float* G = g_G[isX ? 0 : 1];
        const int row0 = m0 + (lane >> 2);
        const int col0 = (lane & 3) * 2;
        #pragma unroll
        for (int nt = 0; nt < 16; ++nt)
            #pragma unroll
            for (int i = 0; i < 4; ++i) {
                const int rr = row0 + (i >> 1) * 8;
                const int cc = nt * 8 + col0 + (i & 1);
                atomicAdd(&G[rr * DIM + cc], acc[nt][i]);
            }
    }

    // ---- ticket: last block finalizes ----
    __threadfence();
    if (tid == 0) s_last = atomicAdd(&g_ticket, 1u);
    __syncthreads();
    if (s_last != NBLOCKS - 1) return;
    __threadfence();   // acquire side: make all blocks' merges visible

    // Frobenius product <G0, G1> in double (16 float4 pairs per thread)
    const float4* G0 = reinterpret_cast<const float4*>(g_G[0]);
    const float4* G1 = reinterpret_cast<const float4*>(g_G[1]);
    double s1 = 0.0;
    #pragma unroll
    for (int j = 0; j < 16; ++j) {
        const int i = tid + 256 * j;
        const float4 a = G0[i], b = G1[i];
        s1 += (double)a.x * b.x + (double)a.y * b.y
            + (double)a.z * b.z + (double)a.w * b.w;
    }
    sred[tid] = s1;
    __syncthreads();
    for (int s = 128; s; s >>= 1) {
        if (tid < s) sred[tid] += sred[tid + s];
        __syncthreads();
    }
    if (tid == 0) {
        const double loss =
            (sred[0] - (double)g_S2) / ((double)NROWS * (double)(NROWS - 1))
            - 2.0 * (double)g_S3 / (double)NROWS;
        out[0] = (float)loss;
    }

    // ---- re-zero scratch so the next graph replay starts clean ----
    float4 z = make_float4(0.f, 0.f, 0.f, 0.f);
    float4* Z0 = reinterpret_cast<float4*>(g_G[0]);
    float4* Z1 = reinterpret_cast<float4*>(g_G[1]);
    #pragma unroll
    for (int j = 0; j < 16; ++j) {
        Z0[tid + 256 * j] = z;
        Z1[tid + 256 * j] = z;
    }
    if (tid == 0) { g_S2 = 0.0f; g_S3 = 0.0f; g_ticket = 0u; }
}

// ---------------------------------------------------------------------------
extern "C" void kernel_launch(void* const* d_in, const int* in_sizes, int n_in,
                              void* d_out, int out_size) {
    const float* X = (const float*)d_in[0];
    const float* Y = (const float*)d_in[1];
    float* out = (float*)d_out;

    static bool attr_set = false;   // idempotent host-side attribute
    if (!attr_set) {
        cudaFuncSetAttribute(gram_all,
                             cudaFuncAttributeMaxDynamicSharedMemorySize, SMEM_TOTAL);
        attr_set = true;
    }

    gram_all<<<NBLOCKS, 256, SMEM_TOTAL>>>(X, Y, out);
}

// round 6
// speedup vs baseline: 1.1145x; 1.1145x over previous
#include <cuda_runtime.h>
#include <cuda_bf16.h>
#include <cstdint>

#define NROWS 8192
#define DIM   128
#define CHUNK 128                  // samples per tile
#define NBLOCKS 128                // b<64: X chunk b (+diag); b>=64: Y chunk b-64
#define NTHREADS 512               // 16 warps

// ---------------- device-global scratch (no allocations allowed) -----------
// Zero at load; every launch restores the zeroed state before exiting.
__device__ float    g_G[2][DIM * DIM];  // [0]=X^T X, [1]=Y^T Y
__device__ float    g_S2;               // sum d_i^2
__device__ float    g_S3;               // sum d_i
__device__ unsigned g_ticket;

// ---------------- helpers ---------------------------------------------------
__device__ __forceinline__ uint32_t smem_u32(const void* p) {
    uint32_t a;
    asm("{ .reg .u64 t; cvta.to.shared.u64 t, %1; cvt.u32.u64 %0, t; }" : "=r"(a) : "l"(p));
    return a;
}

// Tile stored SAMPLE-major: S[k][d]; two 16KB subtiles by d>>6; SW128 swizzle.
__device__ __forceinline__ uint32_t toff(int k, int d) {
    uint32_t o = (uint32_t)(k * 128 + (d & 63) * 2);
    o ^= (o >> 3) & 0x70;
    return (uint32_t)((d >> 6) * 16384) + o;
}

#define LO_OFF     32768           // lo tile after hi tile (each 32KB)
#define SMEM_TOTAL 65536

__device__ __forceinline__ void ldsm4t(uint32_t* r, uint32_t addr) {
    asm volatile("ldmatrix.sync.aligned.m8n8.x4.trans.shared.b16 {%0,%1,%2,%3}, [%4];"
                 : "=r"(r[0]), "=r"(r[1]), "=r"(r[2]), "=r"(r[3]) : "r"(addr));
}

__device__ __forceinline__ void mma_bf16(float* d, const uint32_t* a,
                                         uint32_t b0, uint32_t b1) {
    asm volatile(
        "mma.sync.aligned.m16n8k16.row.col.f32.bf16.bf16.f32 "
        "{%0,%1,%2,%3}, {%4,%5,%6,%7}, {%8,%9}, {%0,%1,%2,%3};"
        : "+f"(d[0]), "+f"(d[1]), "+f"(d[2]), "+f"(d[3])
        : "r"(a[0]), "r"(a[1]), "r"(a[2]), "r"(a[3]), "r"(b0), "r"(b1));
}

// Non-returning vector atomic add (sm_90+): halves merge op count.
__device__ __forceinline__ void red_add_v2(float* p, float a, float b) {
    asm volatile("red.global.add.v2.f32 [%0], {%1, %2};"
                 :: "l"(p), "f"(a), "f"(b) : "memory");
}

// ---------------------------------------------------------------------------
// Single fused kernel: convert(+diag) -> tensor-core Gram -> vec-atomic merge
// -> ticket -> last block: Frobenius reduce + combine + write + re-zero.
// 16 warps: warp w owns output slab rows [(w&7)*16, +16) x cols [(w>>3)*64, +64).
// ---------------------------------------------------------------------------
__global__ __launch_bounds__(NTHREADS, 1)
void gram_all(const float* __restrict__ X, const float* __restrict__ Y,
              float* __restrict__ out) {
    extern __shared__ char smem[];
    __shared__ double   sred[NTHREADS];
    __shared__ unsigned s_last;

    const uint32_t sb = smem_u32(smem);
    const int tid  = threadIdx.x;
    const int w    = tid >> 5;
    const int lane = tid & 31;

    const bool isX  = blockIdx.x < (NBLOCKS / 2);
    const int chunk = isX ? blockIdx.x : blockIdx.x - NBLOCKS / 2;
    const float* base  = (isX ? X : Y) + (size_t)chunk * CHUNK * DIM;
    const float* ybase = Y + (size_t)chunk * CHUNK * DIM;   // diag (X blocks)

    // ldmatrix per-lane tile-row selectors
    const int lr    = lane & 7;
    const int a_kad = (lane & 16) ? 8 : 0;
    const int a_mad = (lane & 8)  ? 8 : 0;
    const int b_kad = (lane & 8)  ? 8 : 0;
    const int b_nad = (lane & 16) ? 8 : 0;
    const int m0    = (w & 7) * 16;        // warp's output row slab
    const int nbase = (w >> 3) * 64;       // warp's output column half

    // ---- convert fp32 -> bf16 hi/lo tiles; X blocks also compute diag ----
    float s2 = 0.0f, s3 = 0.0f;
    #pragma unroll
    for (int it = 0; it < 8; ++it) {
        const int r = w + 16 * it;                    // sample row
        const float4 v = *reinterpret_cast<const float4*>(base + r * DIM + lane * 4);
        __nv_bfloat162 h01 = __floats2bfloat162_rn(v.x, v.y);
        __nv_bfloat162 h23 = __floats2bfloat162_rn(v.z, v.w);
        __nv_bfloat162 l01 = __floats2bfloat162_rn(v.x - __bfloat162float(h01.x),
                                                   v.y - __bfloat162float(h01.y));
        __nv_bfloat162 l23 = __floats2bfloat162_rn(v.z - __bfloat162float(h23.x),
                                                   v.w - __bfloat162float(h23.y));
        const uint32_t o = toff(r, lane * 4);
        uint2 hv, lv;
        hv.x = *reinterpret_cast<uint32_t*>(&h01);
        hv.y = *reinterpret_cast<uint32_t*>(&h23);
        lv.x = *reinterpret_cast<uint32_t*>(&l01);
        lv.y = *reinterpret_cast<uint32_t*>(&l23);
        *reinterpret_cast<uint2*>(smem + o)          = hv;
        *reinterpret_cast<uint2*>(smem + LO_OFF + o) = lv;

        if (isX) {                                    // diag: d_r = <x_r, y_r>
            const float4 u = *reinterpret_cast<const float4*>(ybase + r * DIM + lane * 4);
            float d = v.x * u.x + v.y * u.y + v.z * u.z + v.w * u.w;
            #pragma unroll
            for (int o2 = 16; o2; o2 >>= 1) d += __shfl_xor_sync(0xffffffffu, d, o2);
            s3 += d;
            s2 += d * d;
        }
    }
    if (isX && lane == 0) {
        atomicAdd(&g_S3, s3);
        atomicAdd(&g_S2, s2);
    }
    __syncthreads();

    // ---- MMA mainloop: acc[nt][i], nt = 0..7 (8-col tiles in this half) ----
    float acc[8][4];
    #pragma unroll
    for (int nt = 0; nt < 8; ++nt)
        #pragma unroll
        for (int i = 0; i < 4; ++i) acc[nt][i] = 0.0f;

    for (int ks = 0; ks < 8; ++ks) {
        const int k0 = ks * 16;
        uint32_t ahi[4], alo[4];
        const uint32_t aoff = toff(k0 + lr + a_kad, m0 + a_mad);
        ldsm4t(ahi, sb + aoff);
        ldsm4t(alo, sb + LO_OFF + aoff);

        #pragma unroll
        for (int ntp = 0; ntp < 4; ++ntp) {
            const int n0 = nbase + ntp * 16;
            uint32_t bhi[4], blo[4];
            const uint32_t boff = toff(k0 + lr + b_kad, n0 + b_nad);
            ldsm4t(bhi, sb + boff);
            ldsm4t(blo, sb + LO_OFF + boff);
            mma_bf16(acc[2 * ntp], ahi, bhi[0], bhi[1]);
            mma_bf16(acc[2 * ntp], ahi, blo[0], blo[1]);
            mma_bf16(acc[2 * ntp], alo, bhi[0], bhi[1]);
            mma_bf16(acc[2 * ntp + 1], ahi, bhi[2], bhi[3]);
            mma_bf16(acc[2 * ntp + 1], ahi, blo[2], blo[3]);
            mma_bf16(acc[2 * ntp + 1], alo, bhi[2], bhi[3]);
        }
    }

    // ---- merge partial Gram with v2 vector atomics ----
    {
        float* G = g_G[isX ? 0 : 1];
        const int row0 = m0 + (lane >> 2);
        const int col0 = (lane & 3) * 2;
        #pragma unroll
        for (int nt = 0; nt < 8; ++nt) {
            const int cc = nbase + nt * 8 + col0;
            red_add_v2(&G[row0 * DIM + cc],       acc[nt][0], acc[nt][1]);
            red_add_v2(&G[(row0 + 8) * DIM + cc], acc[nt][2], acc[nt][3]);
        }
    }

    // ---- ticket: last block finalizes ----
    __threadfence();
    if (tid == 0) s_last = atomicAdd(&g_ticket, 1u);
    __syncthreads();
    if (s_last != NBLOCKS - 1) return;
    __threadfence();   // acquire: all blocks' merges visible

    // Frobenius product <G0, G1> in double (8 float4 pairs per thread)
    const float4* G0 = reinterpret_cast<const float4*>(g_G[0]);
    const float4* G1 = reinterpret_cast<const float4*>(g_G[1]);
    double s1 = 0.0;
    #pragma unroll
    for (int j = 0; j < 8; ++j) {
        const int i = tid + NTHREADS * j;
        const float4 a = G0[i], b = G1[i];
        s1 += (double)a.x * b.x + (double)a.y * b.y
            + (double)a.z * b.z + (double)a.w * b.w;
    }
    sred[tid] = s1;
    __syncthreads();
    for (int s = NTHREADS / 2; s; s >>= 1) {
        if (tid < s) sred[tid] += sred[tid + s];
        __syncthreads();
    }
    if (tid == 0) {
        const double loss =
            (sred[0] - (double)g_S2) / ((double)NROWS * (double)(NROWS - 1))
            - 2.0 * (double)g_S3 / (double)NROWS;
        out[0] = (float)loss;
    }

    // ---- re-zero scratch so the next graph replay starts clean ----
    float4 z = make_float4(0.f, 0.f, 0.f, 0.f);
    float4* Z0 = reinterpret_cast<float4*>(g_G[0]);
    float4* Z1 = reinterpret_cast<float4*>(g_G[1]);
    #pragma unroll
    for (int j = 0; j < 8; ++j) {
        Z0[tid + NTHREADS * j] = z;
        Z1[tid + NTHREADS * j] = z;
    }
    if (tid == 0) { g_S2 = 0.0f; g_S3 = 0.0f; g_ticket = 0u; }
}

// ---------------------------------------------------------------------------
extern "C" void kernel_launch(void* const* d_in, const int* in_sizes, int n_in,
                              void* d_out, int out_size) {
    const float* X = (const float*)d_in[0];
    const float* Y = (const float*)d_in[1];
    float* out = (float*)d_out;

    static bool attr_set = false;   // idempotent host-side attribute
    if (!attr_set) {
        cudaFuncSetAttribute(gram_all,
                             cudaFuncAttributeMaxDynamicSharedMemorySize, SMEM_TOTAL);
        attr_set = true;
    }

    gram_all<<<NBLOCKS, NTHREADS, SMEM_TOTAL>>>(X, Y, out);
}